// round 4
// baseline (speedup 1.0000x reference)
#include <cuda_runtime.h>
#include <math.h>

#define BSZ   4
#define LSEQ  2048
#define DH    1024
#define MROWS (BSZ * LSEQ)   // 8192

// Scratch for Q, K, V projections (3 x 33.5 MB). Static device arrays: no runtime allocs.
__device__ float g_Q[(size_t)MROWS * DH];
__device__ float g_K[(size_t)MROWS * DH];
__device__ float g_V[(size_t)MROWS * DH];

// ---------------------------------------------------------------------------
// GEMM NT: C[m,n] = scale * sum_k A[m,k]*B[n,k] (+ bias[n]) (+ causal -999)
// A: M x K row-major, B: N x K row-major (both K-contiguous).
// 128x128 block tile, BK=16, 256 threads, 8x8 micro-tile, double-buffered smem.
// ---------------------------------------------------------------------------
__global__ __launch_bounds__(256, 2) void gemm_nt(
    const float* __restrict__ A, const float* __restrict__ Bm,
    const float* __restrict__ bias, float* __restrict__ C,
    int M, int N, int K,
    long long sA, long long sB, long long sC,
    float scale, int causal)
{
    A  += (long long)blockIdx.z * sA;
    Bm += (long long)blockIdx.z * sB;
    C  += (long long)blockIdx.z * sC;

    __shared__ float As[2][16][128];   // [buf][k][m]
    __shared__ float Bs[2][16][128];   // [buf][k][n]

    const int tid = threadIdx.x;
    const int tx  = tid & 15;       // n micro-tile
    const int ty  = tid >> 4;       // m micro-tile
    const int m0  = blockIdx.y * 128;
    const int n0  = blockIdx.x * 128;

    // Per-thread global-load coordinates (one 128-row tile slice per thread).
    const int r0 = tid >> 1;                 // 0..127
    const int kc0 = (tid & 1) << 3;          // 0 or 8

    float acc[8][8];
#pragma unroll
    for (int i = 0; i < 8; i++)
#pragma unroll
        for (int j = 0; j < 8; j++) acc[i][j] = 0.0f;

    // Prologue: load tile 0 into buffer 0.
    {
        float4 va0 = *(const float4*)&A [(size_t)(m0 + r0) * K + 0 + kc0];
        float4 va1 = *(const float4*)&A [(size_t)(m0 + r0) * K + 0 + kc0 + 4];
        float4 vb0 = *(const float4*)&Bm[(size_t)(n0 + r0) * K + 0 + kc0];
        float4 vb1 = *(const float4*)&Bm[(size_t)(n0 + r0) * K + 0 + kc0 + 4];
        As[0][kc0 + 0][r0] = va0.x; As[0][kc0 + 1][r0] = va0.y;
        As[0][kc0 + 2][r0] = va0.z; As[0][kc0 + 3][r0] = va0.w;
        As[0][kc0 + 4][r0] = va1.x; As[0][kc0 + 5][r0] = va1.y;
        As[0][kc0 + 6][r0] = va1.z; As[0][kc0 + 7][r0] = va1.w;
        Bs[0][kc0 + 0][r0] = vb0.x; Bs[0][kc0 + 1][r0] = vb0.y;
        Bs[0][kc0 + 2][r0] = vb0.z; Bs[0][kc0 + 3][r0] = vb0.w;
        Bs[0][kc0 + 4][r0] = vb1.x; Bs[0][kc0 + 5][r0] = vb1.y;
        Bs[0][kc0 + 6][r0] = vb1.z; Bs[0][kc0 + 7][r0] = vb1.w;
    }
    __syncthreads();

    int buf = 0;
    for (int k0 = 0; k0 < K; k0 += 16) {
        // Prefetch next tile into registers while computing on current buffer.
        float4 va0, va1, vb0, vb1;
        const bool have_next = (k0 + 16 < K);
        if (have_next) {
            int kn = k0 + 16;
            va0 = *(const float4*)&A [(size_t)(m0 + r0) * K + kn + kc0];
            va1 = *(const float4*)&A [(size_t)(m0 + r0) * K + kn + kc0 + 4];
            vb0 = *(const float4*)&Bm[(size_t)(n0 + r0) * K + kn + kc0];
            vb1 = *(const float4*)&Bm[(size_t)(n0 + r0) * K + kn + kc0 + 4];
        }

#pragma unroll
        for (int k = 0; k < 16; k++) {
            float4 a0 = *(const float4*)&As[buf][k][ty * 8];
            float4 a1 = *(const float4*)&As[buf][k][ty * 8 + 4];
            float4 b0 = *(const float4*)&Bs[buf][k][tx * 8];
            float4 b1 = *(const float4*)&Bs[buf][k][tx * 8 + 4];
            float a[8] = {a0.x, a0.y, a0.z, a0.w, a1.x, a1.y, a1.z, a1.w};
            float b[8] = {b0.x, b0.y, b0.z, b0.w, b1.x, b1.y, b1.z, b1.w};
#pragma unroll
            for (int i = 0; i < 8; i++)
#pragma unroll
                for (int j = 0; j < 8; j++)
                    acc[i][j] = fmaf(a[i], b[j], acc[i][j]);
        }

        if (have_next) {
            int nb = buf ^ 1;
            As[nb][kc0 + 0][r0] = va0.x; As[nb][kc0 + 1][r0] = va0.y;
            As[nb][kc0 + 2][r0] = va0.z; As[nb][kc0 + 3][r0] = va0.w;
            As[nb][kc0 + 4][r0] = va1.x; As[nb][kc0 + 5][r0] = va1.y;
            As[nb][kc0 + 6][r0] = va1.z; As[nb][kc0 + 7][r0] = va1.w;
            Bs[nb][kc0 + 0][r0] = vb0.x; Bs[nb][kc0 + 1][r0] = vb0.y;
            Bs[nb][kc0 + 2][r0] = vb0.z; Bs[nb][kc0 + 3][r0] = vb0.w;
            Bs[nb][kc0 + 4][r0] = vb1.x; Bs[nb][kc0 + 5][r0] = vb1.y;
            Bs[nb][kc0 + 6][r0] = vb1.z; Bs[nb][kc0 + 7][r0] = vb1.w;
            __syncthreads();
            buf = nb;
        }
    }

    // Epilogue: scale, bias, causal mask, vectorized store.
#pragma unroll
    for (int i = 0; i < 8; i++) {
        int row = m0 + ty * 8 + i;
        float* crow = &C[(size_t)row * N + n0 + tx * 8];
#pragma unroll
        for (int h = 0; h < 2; h++) {
            float4 o;
            float* av = &acc[i][h * 4];
            int colbase = n0 + tx * 8 + h * 4;
            float v0 = av[0] * scale, v1 = av[1] * scale;
            float v2 = av[2] * scale, v3 = av[3] * scale;
            if (bias) {
                v0 += bias[colbase + 0]; v1 += bias[colbase + 1];
                v2 += bias[colbase + 2]; v3 += bias[colbase + 3];
            }
            if (causal) {
                v0 += (colbase + 0 > row) ? -999.0f : 0.0f;
                v1 += (colbase + 1 > row) ? -999.0f : 0.0f;
                v2 += (colbase + 2 > row) ? -999.0f : 0.0f;
                v3 += (colbase + 3 > row) ? -999.0f : 0.0f;
            }
            o.x = v0; o.y = v1; o.z = v2; o.w = v3;
            *(float4*)&crow[h * 4] = o;
        }
    }
}

// ---------------------------------------------------------------------------
// GEMM NN: C[m,n] = sum_k A[m,k]*B[k,n]
// A: M x K row-major, B: K x N row-major. Double-buffered smem.
// ---------------------------------------------------------------------------
__global__ __launch_bounds__(256, 2) void gemm_nn(
    const float* __restrict__ A, const float* __restrict__ Bm,
    float* __restrict__ C, int M, int N, int K,
    long long sA, long long sB, long long sC)
{
    A  += (long long)blockIdx.z * sA;
    Bm += (long long)blockIdx.z * sB;
    C  += (long long)blockIdx.z * sC;

    __shared__ float As[2][16][128];   // [buf][k][m]
    __shared__ float Bs[2][16][128];   // [buf][k][n]

    const int tid = threadIdx.x;
    const int tx  = tid & 15;
    const int ty  = tid >> 4;
    const int m0  = blockIdx.y * 128;
    const int n0  = blockIdx.x * 128;

    // A-tile thread coords (128 rows x 16 k): 2 float4 per thread
    const int ar  = tid >> 1;
    const int akc = (tid & 1) << 3;
    // B-tile thread coords (16 k x 128 n): 2 float4 per thread
    const int br0 = tid >> 4;              // 0..15
    const int bc0 = (tid & 15) << 3;       // 0..120

    float acc[8][8];
#pragma unroll
    for (int i = 0; i < 8; i++)
#pragma unroll
        for (int j = 0; j < 8; j++) acc[i][j] = 0.0f;

    // Prologue
    {
        float4 va0 = *(const float4*)&A[(size_t)(m0 + ar) * K + akc];
        float4 va1 = *(const float4*)&A[(size_t)(m0 + ar) * K + akc + 4];
        As[0][akc + 0][ar] = va0.x; As[0][akc + 1][ar] = va0.y;
        As[0][akc + 2][ar] = va0.z; As[0][akc + 3][ar] = va0.w;
        As[0][akc + 4][ar] = va1.x; As[0][akc + 5][ar] = va1.y;
        As[0][akc + 6][ar] = va1.z; As[0][akc + 7][ar] = va1.w;
        float4 vb0 = *(const float4*)&Bm[(size_t)br0 * N + n0 + bc0];
        float4 vb1 = *(const float4*)&Bm[(size_t)br0 * N + n0 + bc0 + 4];
        *(float4*)&Bs[0][br0][bc0]     = vb0;
        *(float4*)&Bs[0][br0][bc0 + 4] = vb1;
    }
    __syncthreads();

    int buf = 0;
    for (int k0 = 0; k0 < K; k0 += 16) {
        float4 va0, va1, vb0, vb1;
        const bool have_next = (k0 + 16 < K);
        if (have_next) {
            int kn = k0 + 16;
            va0 = *(const float4*)&A[(size_t)(m0 + ar) * K + kn + akc];
            va1 = *(const float4*)&A[(size_t)(m0 + ar) * K + kn + akc + 4];
            vb0 = *(const float4*)&Bm[(size_t)(kn + br0) * N + n0 + bc0];
            vb1 = *(const float4*)&Bm[(size_t)(kn + br0) * N + n0 + bc0 + 4];
        }

#pragma unroll
        for (int k = 0; k < 16; k++) {
            float4 a0 = *(const float4*)&As[buf][k][ty * 8];
            float4 a1 = *(const float4*)&As[buf][k][ty * 8 + 4];
            float4 b0 = *(const float4*)&Bs[buf][k][tx * 8];
            float4 b1 = *(const float4*)&Bs[buf][k][tx * 8 + 4];
            float a[8] = {a0.x, a0.y, a0.z, a0.w, a1.x, a1.y, a1.z, a1.w};
            float b[8] = {b0.x, b0.y, b0.z, b0.w, b1.x, b1.y, b1.z, b1.w};
#pragma unroll
            for (int i = 0; i < 8; i++)
#pragma unroll
                for (int j = 0; j < 8; j++)
                    acc[i][j] = fmaf(a[i], b[j], acc[i][j]);
        }

        if (have_next) {
            int nb = buf ^ 1;
            As[nb][akc + 0][ar] = va0.x; As[nb][akc + 1][ar] = va0.y;
            As[nb][akc + 2][ar] = va0.z; As[nb][akc + 3][ar] = va0.w;
            As[nb][akc + 4][ar] = va1.x; As[nb][akc + 5][ar] = va1.y;
            As[nb][akc + 6][ar] = va1.z; As[nb][akc + 7][ar] = va1.w;
            *(float4*)&Bs[nb][br0][bc0]     = vb0;
            *(float4*)&Bs[nb][br0][bc0 + 4] = vb1;
            __syncthreads();
            buf = nb;
        }
    }

#pragma unroll
    for (int i = 0; i < 8; i++) {
        int row = m0 + ty * 8 + i;
        float* crow = &C[(size_t)row * N + n0 + tx * 8];
        float4 o0 = {acc[i][0], acc[i][1], acc[i][2], acc[i][3]};
        float4 o1 = {acc[i][4], acc[i][5], acc[i][6], acc[i][7]};
        *(float4*)&crow[0] = o0;
        *(float4*)&crow[4] = o1;
    }
}

// ---------------------------------------------------------------------------
// Row softmax over 2048 elements, in place. One block per row, 256 threads,
// 8 elements per thread in registers; warp-shuffle reductions.
// ---------------------------------------------------------------------------
__global__ __launch_bounds__(256) void softmax_rows(float* __restrict__ w)
{
    float* p = w + (size_t)blockIdx.x * LSEQ;
    const int t    = threadIdx.x;
    const int lane = t & 31;
    const int wrp  = t >> 5;
    __shared__ float red[8];

    float v[8];
    float mx = -INFINITY;
#pragma unroll
    for (int i = 0; i < 8; i++) {
        v[i] = p[t + 256 * i];
        mx = fmaxf(mx, v[i]);
    }
#pragma unroll
    for (int s = 16; s > 0; s >>= 1)
        mx = fmaxf(mx, __shfl_xor_sync(0xffffffffu, mx, s));
    if (lane == 0) red[wrp] = mx;
    __syncthreads();
    mx = red[0];
#pragma unroll
    for (int i = 1; i < 8; i++) mx = fmaxf(mx, red[i]);

    float sum = 0.0f;
#pragma unroll
    for (int i = 0; i < 8; i++) {
        v[i] = __expf(v[i] - mx);
        sum += v[i];
    }
#pragma unroll
    for (int s = 16; s > 0; s >>= 1)
        sum += __shfl_xor_sync(0xffffffffu, sum, s);
    __syncthreads();
    if (lane == 0) red[wrp] = sum;
    __syncthreads();
    sum = 0.0f;
#pragma unroll
    for (int i = 0; i < 8; i++) sum += red[i];

    float inv = 1.0f / sum;
#pragma unroll
    for (int i = 0; i < 8; i++)
        p[t + 256 * i] = v[i] * inv;
}

// ---------------------------------------------------------------------------
// Launch: QKV projections -> scores(+mask) -> softmax -> out = wts @ V
// Output layout: [out (B,L,D)] then [wts (B,L,L)], concatenated fp32.
// ---------------------------------------------------------------------------
extern "C" void kernel_launch(void* const* d_in, const int* in_sizes, int n_in,
                              void* d_out, int out_size)
{
    (void)in_sizes; (void)n_in; (void)out_size;
    const float* x  = (const float*)d_in[0];
    const float* Wq = (const float*)d_in[1];
    const float* bq = (const float*)d_in[2];
    const float* Wk = (const float*)d_in[3];
    const float* bk = (const float*)d_in[4];
    const float* Wv = (const float*)d_in[5];
    const float* bv = (const float*)d_in[6];

    float* out = (float*)d_out;
    float* wts = out + (size_t)MROWS * DH;

    float *Q, *K, *V;
    cudaGetSymbolAddress((void**)&Q, g_Q);
    cudaGetSymbolAddress((void**)&K, g_K);
    cudaGetSymbolAddress((void**)&V, g_V);

    dim3 blk(256);

    // QKV projections: (8192 x 1024) = (8192 x 1024) @ (1024 x 1024)^T + b
    dim3 gq(DH / 128, MROWS / 128);                 // (8, 64)
    gemm_nt<<<gq, blk>>>(x, Wq, bq, Q, MROWS, DH, DH, 0, 0, 0, 1.0f, 0);
    gemm_nt<<<gq, blk>>>(x, Wk, bk, K, MROWS, DH, DH, 0, 0, 0, 1.0f, 0);
    gemm_nt<<<gq, blk>>>(x, Wv, bv, V, MROWS, DH, DH, 0, 0, 0, 1.0f, 0);

    // scores = Q K^T / 32 + causal(-999), written into wts region
    dim3 gs(LSEQ / 128, LSEQ / 128, BSZ);           // (16, 16, 4)
    gemm_nt<<<gs, blk>>>(Q, K, nullptr, wts, LSEQ, LSEQ, DH,
                         (long long)LSEQ * DH, (long long)LSEQ * DH,
                         (long long)LSEQ * LSEQ, 1.0f / 32.0f, 1);

    // softmax over each of the 8192 rows of length 2048, in place
    softmax_rows<<<MROWS, 256>>>(wts);

    // out = wts @ V
    dim3 go(DH / 128, LSEQ / 128, BSZ);             // (8, 16, 4)
    gemm_nn<<<go, blk>>>(wts, V, out, LSEQ, DH, LSEQ,
                         (long long)LSEQ * LSEQ, (long long)LSEQ * DH,
                         (long long)LSEQ * DH);
}

// round 8
// speedup vs baseline: 2.3145x; 2.3145x over previous
#include <cuda_runtime.h>
#include <cuda_bf16.h>
#include <math.h>
#include <stdint.h>

#define BSZ   4
#define LSEQ  2048
#define DH    1024
#define MROWS (BSZ * LSEQ)   // 8192

// ---------------------------------------------------------------------------
// bf16 hi/lo scratch (static device arrays: no runtime allocs)
// ---------------------------------------------------------------------------
__device__ __nv_bfloat16 g_xh[(size_t)MROWS * DH],  g_xl[(size_t)MROWS * DH];
__device__ __nv_bfloat16 g_Wqh[(size_t)DH * DH],    g_Wql[(size_t)DH * DH];
__device__ __nv_bfloat16 g_Wkh[(size_t)DH * DH],    g_Wkl[(size_t)DH * DH];
__device__ __nv_bfloat16 g_Wvh[(size_t)DH * DH],    g_Wvl[(size_t)DH * DH];
__device__ __nv_bfloat16 g_Qh[(size_t)MROWS * DH],  g_Ql[(size_t)MROWS * DH];
__device__ __nv_bfloat16 g_Kh[(size_t)MROWS * DH],  g_Kl[(size_t)MROWS * DH];
__device__ __nv_bfloat16 g_Vth[(size_t)MROWS * DH], g_Vtl[(size_t)MROWS * DH]; // [b][d][l]
__device__ __nv_bfloat16 g_Sh[(size_t)MROWS * LSEQ], g_Sl[(size_t)MROWS * LSEQ];

// ---------------------------------------------------------------------------
// PTX helpers — ONLY arch-neutral instructions (sm_80+ baseline ISA):
// cp.async, ldmatrix, mma.sync. No tcgen05 (requires sm_103a target).
// ---------------------------------------------------------------------------
__device__ __forceinline__ uint32_t smem_to_u32(const void* p) {
    uint32_t a;
    asm("{ .reg .u64 t; cvta.to.shared.u64 t, %1; cvt.u32.u64 %0, t; }"
        : "=r"(a) : "l"(p));
    return a;
}
#define CP_ASYNC16(smem, gptr) \
    asm volatile("cp.async.ca.shared.global [%0], [%1], 16;" \
                 :: "r"(smem), "l"(gptr))
#define CP_COMMIT() asm volatile("cp.async.commit_group;")
#define CP_WAIT(n)  asm volatile("cp.async.wait_group %0;" :: "n"(n))

#define LDMATRIX_X4(r, addr) \
    asm volatile("ldmatrix.sync.aligned.m8n8.x4.shared.b16 {%0,%1,%2,%3}, [%4];" \
                 : "=r"((r)[0]), "=r"((r)[1]), "=r"((r)[2]), "=r"((r)[3]) \
                 : "r"(addr))

#define MMA_BF16(c, a, b0v, b1v) \
    asm volatile("mma.sync.aligned.m16n8k16.row.col.f32.bf16.bf16.f32 " \
                 "{%0,%1,%2,%3}, {%4,%5,%6,%7}, {%8,%9}, {%0,%1,%2,%3};" \
                 : "+f"((c)[0]), "+f"((c)[1]), "+f"((c)[2]), "+f"((c)[3]) \
                 : "r"((a)[0]), "r"((a)[1]), "r"((a)[2]), "r"((a)[3]), \
                   "r"(b0v), "r"(b1v))

// ---------------------------------------------------------------------------
// Split-bf16 tensor-core GEMM (NT): C = scale*(A·B^T) + bias + causal
// A = Ah+Al (M x K bf16, K-major), B = Bh+Bl (N x K bf16, K-major).
// CTA tile 128x128, BK=32, 8 warps (2x4), warp tile 64x32, cp.async 2-stage.
// smem per matrix tile: 128 rows x 80B (32 bf16 padded) = 10240 B; 4 matrices
// x 2 stages = 81920 B.
// mode 0: Cf[row*ldc+col] fp32
// mode 1: split-store bf16 hi/lo to Ch/Cl[row*ldc+col]
// mode 2: split-store transposed-batched: Ch[(b*DH+col)*LSEQ + l]
// ---------------------------------------------------------------------------
#define ROWB      80
#define MAT_BYTES 10240
#define STG_BYTES (4 * MAT_BYTES)
#define SMEM_BYTES (2 * STG_BYTES)

__global__ __launch_bounds__(256) void gemm_mma(
    const __nv_bfloat16* __restrict__ Ah, const __nv_bfloat16* __restrict__ Al,
    const __nv_bfloat16* __restrict__ Bh, const __nv_bfloat16* __restrict__ Bl,
    const float* __restrict__ bias,
    float* __restrict__ Cf, __nv_bfloat16* __restrict__ Ch, __nv_bfloat16* __restrict__ Cl,
    int K, int ldc,
    long long sA, long long sB, long long sC,
    float scale, int causal, int mode)
{
    extern __shared__ char smem[];
    const uint32_t sbase = smem_to_u32(smem);
    const int tid  = threadIdx.x;
    const int wid  = tid >> 5;
    const int lane = tid & 31;
    const int wm   = wid >> 2;       // 0..1 -> m offset wm*64
    const int wn   = wid & 3;        // 0..3 -> n offset wn*32
    const int m0   = blockIdx.y * 128;
    const int n0   = blockIdx.x * 128;
    const int z    = blockIdx.z;

    const __nv_bfloat16* pAh = Ah + z * sA + (size_t)m0 * K;
    const __nv_bfloat16* pAl = Al + z * sA + (size_t)m0 * K;
    const __nv_bfloat16* pBh = Bh + z * sB + (size_t)n0 * K;
    const __nv_bfloat16* pBl = Bl + z * sB + (size_t)n0 * K;

    // Per-thread cp.async geometry: 2 chunks per matrix per stage.
    // e = tid + half*256: row = e>>2 (0..127), c = e&3 (16B chunk within 64B of k)
    auto issue = [&](int i) {
        const int k0 = i << 5;
        const uint32_t st = sbase + (i & 1) * STG_BYTES;
#pragma unroll
        for (int half = 0; half < 2; half++) {
            int e = tid + half * 256;
            int r = e >> 2, c = e & 3;
            uint32_t so = st + (uint32_t)(r * ROWB + c * 16);
            size_t go = (size_t)r * K + k0 + c * 8;
            CP_ASYNC16(so,                 pAh + go);
            CP_ASYNC16(so + 1 * MAT_BYTES, pAl + go);
            CP_ASYNC16(so + 2 * MAT_BYTES, pBh + go);
            CP_ASYNC16(so + 3 * MAT_BYTES, pBl + go);
        }
        CP_COMMIT();
    };

    float acc[4][4][4];
#pragma unroll
    for (int mi = 0; mi < 4; mi++)
#pragma unroll
        for (int ni = 0; ni < 4; ni++)
#pragma unroll
            for (int q = 0; q < 4; q++) acc[mi][ni][q] = 0.0f;

    const int niters = K >> 5;
    issue(0);

    for (int i = 0; i < niters; i++) {
        if (i + 1 < niters) { issue(i + 1); CP_WAIT(1); }
        else                { CP_WAIT(0); }
        __syncthreads();

        const uint32_t st = sbase + (i & 1) * STG_BYTES;
#pragma unroll
        for (int ks = 0; ks < 2; ks++) {
            uint32_t ah[4][4], al[4][4], bh[4][2], bl[4][2];
            const uint32_t kcol = (uint32_t)((ks * 2 + (lane >> 4)) * 16);
#pragma unroll
            for (int mi = 0; mi < 4; mi++) {
                uint32_t addr = st + (uint32_t)((wm * 64 + mi * 16 + (lane & 15)) * ROWB) + kcol;
                LDMATRIX_X4(ah[mi], addr);
                LDMATRIX_X4(al[mi], addr + MAT_BYTES);
            }
#pragma unroll
            for (int p = 0; p < 2; p++) {
                uint32_t addr = st + 2 * MAT_BYTES +
                    (uint32_t)((wn * 32 + p * 16 + (lane & 15)) * ROWB) + kcol;
                uint32_t t[4];
                LDMATRIX_X4(t, addr);
                bh[p * 2 + 0][0] = t[0]; bh[p * 2 + 0][1] = t[2];
                bh[p * 2 + 1][0] = t[1]; bh[p * 2 + 1][1] = t[3];
                LDMATRIX_X4(t, addr + MAT_BYTES);
                bl[p * 2 + 0][0] = t[0]; bl[p * 2 + 0][1] = t[2];
                bl[p * 2 + 1][0] = t[1]; bl[p * 2 + 1][1] = t[3];
            }
#pragma unroll
            for (int mi = 0; mi < 4; mi++)
#pragma unroll
                for (int ni = 0; ni < 4; ni++) {
                    MMA_BF16(acc[mi][ni], ah[mi], bh[ni][0], bh[ni][1]);
                    MMA_BF16(acc[mi][ni], ah[mi], bl[ni][0], bl[ni][1]);
                    MMA_BF16(acc[mi][ni], al[mi], bh[ni][0], bh[ni][1]);
                }
        }
        __syncthreads();
    }

    // ---- Epilogue ----
#pragma unroll
    for (int mi = 0; mi < 4; mi++) {
#pragma unroll
        for (int ni = 0; ni < 4; ni++) {
            const int row0 = m0 + wm * 64 + mi * 16 + (lane >> 2);
            const int col0 = n0 + wn * 32 + ni * 8 + 2 * (lane & 3);
            float bsum0 = bias ? bias[col0]     : 0.0f;
            float bsum1 = bias ? bias[col0 + 1] : 0.0f;
#pragma unroll
            for (int h = 0; h < 2; h++) {
                const int row = row0 + h * 8;
                float v0 = acc[mi][ni][h * 2 + 0] * scale + bsum0;
                float v1 = acc[mi][ni][h * 2 + 1] * scale + bsum1;
                if (causal) {
                    v0 += (col0     > row) ? -999.0f : 0.0f;
                    v1 += (col0 + 1 > row) ? -999.0f : 0.0f;
                }
                if (mode == 0) {
                    float2 o = {v0, v1};
                    *(float2*)(Cf + z * sC + (size_t)row * ldc + col0) = o;
                } else if (mode == 1) {
                    __nv_bfloat16 h0 = __float2bfloat16(v0);
                    __nv_bfloat16 h1 = __float2bfloat16(v1);
                    __nv_bfloat16 l0 = __float2bfloat16(v0 - __bfloat162float(h0));
                    __nv_bfloat16 l1 = __float2bfloat16(v1 - __bfloat162float(h1));
                    __nv_bfloat162 ph2; ph2.x = h0; ph2.y = h1;
                    __nv_bfloat162 pl2; pl2.x = l0; pl2.y = l1;
                    *(__nv_bfloat162*)(Ch + (size_t)row * ldc + col0) = ph2;
                    *(__nv_bfloat162*)(Cl + (size_t)row * ldc + col0) = pl2;
                } else {
                    const int b = row >> 11, l = row & 2047;
                    __nv_bfloat16 h0 = __float2bfloat16(v0);
                    __nv_bfloat16 h1 = __float2bfloat16(v1);
                    __nv_bfloat16 l0 = __float2bfloat16(v0 - __bfloat162float(h0));
                    __nv_bfloat16 l1 = __float2bfloat16(v1 - __bfloat162float(h1));
                    size_t i0 = ((size_t)b * DH + col0) * LSEQ + l;
                    Ch[i0] = h0; Cl[i0] = l0;
                    Ch[i0 + LSEQ] = h1; Cl[i0 + LSEQ] = l1;
                }
            }
        }
    }
}

// ---------------------------------------------------------------------------
// fp32 -> bf16 hi/lo split (elementwise, vectorized)
// ---------------------------------------------------------------------------
__global__ __launch_bounds__(256) void split_f32(
    const float4* __restrict__ src, __nv_bfloat162* __restrict__ hi,
    __nv_bfloat162* __restrict__ lo, int n4)
{
    int i = blockIdx.x * 256 + threadIdx.x;
    if (i >= n4) return;
    float4 v = src[i];
    __nv_bfloat16 h0 = __float2bfloat16(v.x), h1 = __float2bfloat16(v.y);
    __nv_bfloat16 h2 = __float2bfloat16(v.z), h3 = __float2bfloat16(v.w);
    __nv_bfloat16 l0 = __float2bfloat16(v.x - __bfloat162float(h0));
    __nv_bfloat16 l1 = __float2bfloat16(v.y - __bfloat162float(h1));
    __nv_bfloat16 l2 = __float2bfloat16(v.z - __bfloat162float(h2));
    __nv_bfloat16 l3 = __float2bfloat16(v.w - __bfloat162float(h3));
    __nv_bfloat162 a; a.x = h0; a.y = h1;
    __nv_bfloat162 b; b.x = h2; b.y = h3;
    __nv_bfloat162 c; c.x = l0; c.y = l1;
    __nv_bfloat162 d; d.x = l2; d.y = l3;
    hi[i * 2] = a; hi[i * 2 + 1] = b;
    lo[i * 2] = c; lo[i * 2 + 1] = d;
}

// ---------------------------------------------------------------------------
// Row softmax over 2048 elements, in place.
// ---------------------------------------------------------------------------
__global__ __launch_bounds__(256) void softmax_rows(float* __restrict__ w)
{
    float* p = w + (size_t)blockIdx.x * LSEQ;
    const int t = threadIdx.x, lane = t & 31, wrp = t >> 5;
    __shared__ float red[8];

    float v[8];
    float mx = -INFINITY;
#pragma unroll
    for (int i = 0; i < 8; i++) { v[i] = p[t + 256 * i]; mx = fmaxf(mx, v[i]); }
#pragma unroll
    for (int s = 16; s > 0; s >>= 1) mx = fmaxf(mx, __shfl_xor_sync(0xffffffffu, mx, s));
    if (lane == 0) red[wrp] = mx;
    __syncthreads();
    mx = red[0];
#pragma unroll
    for (int i = 1; i < 8; i++) mx = fmaxf(mx, red[i]);

    float sum = 0.0f;
#pragma unroll
    for (int i = 0; i < 8; i++) { v[i] = __expf(v[i] - mx); sum += v[i]; }
#pragma unroll
    for (int s = 16; s > 0; s >>= 1) sum += __shfl_xor_sync(0xffffffffu, sum, s);
    __syncthreads();
    if (lane == 0) red[wrp] = sum;
    __syncthreads();
    sum = 0.0f;
#pragma unroll
    for (int i = 0; i < 8; i++) sum += red[i];

    float inv = 1.0f / sum;
#pragma unroll
    for (int i = 0; i < 8; i++) p[t + 256 * i] = v[i] * inv;
}

// ---------------------------------------------------------------------------
// Launch
// ---------------------------------------------------------------------------
extern "C" void kernel_launch(void* const* d_in, const int* in_sizes, int n_in,
                              void* d_out, int out_size)
{
    (void)in_sizes; (void)n_in; (void)out_size;
    const float* x  = (const float*)d_in[0];
    const float* Wq = (const float*)d_in[1];
    const float* bq = (const float*)d_in[2];
    const float* Wk = (const float*)d_in[3];
    const float* bk = (const float*)d_in[4];
    const float* Wv = (const float*)d_in[5];
    const float* bv = (const float*)d_in[6];

    float* out = (float*)d_out;
    float* wts = out + (size_t)MROWS * DH;

    cudaFuncSetAttribute(gemm_mma, cudaFuncAttributeMaxDynamicSharedMemorySize, SMEM_BYTES);

    __nv_bfloat16 *xh, *xl, *Wqh, *Wql, *Wkh, *Wkl, *Wvh, *Wvl;
    __nv_bfloat16 *Qh, *Ql, *Kh, *Kl, *Vth, *Vtl, *Sh, *Sl;
    cudaGetSymbolAddress((void**)&xh,  g_xh);  cudaGetSymbolAddress((void**)&xl,  g_xl);
    cudaGetSymbolAddress((void**)&Wqh, g_Wqh); cudaGetSymbolAddress((void**)&Wql, g_Wql);
    cudaGetSymbolAddress((void**)&Wkh, g_Wkh); cudaGetSymbolAddress((void**)&Wkl, g_Wkl);
    cudaGetSymbolAddress((void**)&Wvh, g_Wvh); cudaGetSymbolAddress((void**)&Wvl, g_Wvl);
    cudaGetSymbolAddress((void**)&Qh,  g_Qh);  cudaGetSymbolAddress((void**)&Ql,  g_Ql);
    cudaGetSymbolAddress((void**)&Kh,  g_Kh);  cudaGetSymbolAddress((void**)&Kl,  g_Kl);
    cudaGetSymbolAddress((void**)&Vth, g_Vth); cudaGetSymbolAddress((void**)&Vtl, g_Vtl);
    cudaGetSymbolAddress((void**)&Sh,  g_Sh);  cudaGetSymbolAddress((void**)&Sl,  g_Sl);

    // 1) splits of x and weights
    {
        int n4 = MROWS * DH / 4;
        split_f32<<<(n4 + 255) / 256, 256>>>((const float4*)x,
            (__nv_bfloat162*)xh, (__nv_bfloat162*)xl, n4);
        int w4 = DH * DH / 4;
        split_f32<<<(w4 + 255) / 256, 256>>>((const float4*)Wq,
            (__nv_bfloat162*)Wqh, (__nv_bfloat162*)Wql, w4);
        split_f32<<<(w4 + 255) / 256, 256>>>((const float4*)Wk,
            (__nv_bfloat162*)Wkh, (__nv_bfloat162*)Wkl, w4);
        split_f32<<<(w4 + 255) / 256, 256>>>((const float4*)Wv,
            (__nv_bfloat162*)Wvh, (__nv_bfloat162*)Wvl, w4);
    }

    dim3 blk(256);

    // 2) QKV projections (M=8192, N=1024, K=1024)
    dim3 gq(DH / 128, MROWS / 128, 1);
    gemm_mma<<<gq, blk, SMEM_BYTES>>>(xh, xl, Wqh, Wql, bq,
        nullptr, Qh, Ql, DH, DH, 0, 0, 0, 1.0f, 0, 1);
    gemm_mma<<<gq, blk, SMEM_BYTES>>>(xh, xl, Wkh, Wkl, bk,
        nullptr, Kh, Kl, DH, DH, 0, 0, 0, 1.0f, 0, 1);
    gemm_mma<<<gq, blk, SMEM_BYTES>>>(xh, xl, Wvh, Wvl, bv,
        nullptr, Vth, Vtl, DH, DH, 0, 0, 0, 1.0f, 0, 2);   // V stored transposed

    // 3) scores = Q K^T / 32 + causal(-999)  (per-batch 2048x2048, K=1024)
    dim3 gs(LSEQ / 128, LSEQ / 128, BSZ);
    gemm_mma<<<gs, blk, SMEM_BYTES>>>(Qh, Ql, Kh, Kl, nullptr,
        wts, nullptr, nullptr, DH, LSEQ,
        (long long)LSEQ * DH, (long long)LSEQ * DH, (long long)LSEQ * LSEQ,
        1.0f / 32.0f, 1, 0);

    // 4) softmax rows
    softmax_rows<<<MROWS, 256>>>(wts);

    // 5) split wts
    {
        int n4 = MROWS * LSEQ / 4;
        split_f32<<<(n4 + 255) / 256, 256>>>((const float4*)wts,
            (__nv_bfloat162*)Sh, (__nv_bfloat162*)Sl, n4);
    }

    // 6) out = wts @ V  -> NT with Vt (per-batch 2048x1024, K=2048)
    dim3 go(DH / 128, LSEQ / 128, BSZ);
    gemm_mma<<<go, blk, SMEM_BYTES>>>(Sh, Sl, Vth, Vtl, nullptr,
        out, nullptr, nullptr, LSEQ, DH,
        (long long)LSEQ * LSEQ, (long long)DH * LSEQ, (long long)LSEQ * DH,
        1.0f, 0, 0);
}